// round 15
// baseline (speedup 1.0000x reference)
#include <cuda_runtime.h>
#include <cuda_fp16.h>

#define H 1024
#define W 1024
#define PLANES 24              // 8 * 3
#define THRAW 32               // raw output rows per tile
#define PACK 16                // row-pack stride (.x = r, .y = r+16)
#define TW 128                 // tile cols
#define RE 8                   // cols per thread
#define BX 16
#define BY 16                  // packed rows per tile (compute threads = 256)
#define NCOMP 256
#define NPROD 64               // 2 producer warps
#define THREADS (NCOMP + NPROD)  // 320
#define PROWS (BY + 3)         // 19
#define SCOLS (TW + 8)         // 136 half2 = 34 16B-chunks per row
#define NBX (W / TW)           // 8
#define NBY (H / THRAW)        // 32
#define NT (NBX * NBY * PLANES)       // 6144 tiles
#define GRIDB 444              // 148 SMs x 3 resident blocks
#define NGRP (PROWS * (TW / 4))       // 608 interior float4-groups
#define NHALO (PROWS * 8)             // 152 halo half2 entries

// Even/odd chunk de-interleave: physical slot i (0..31) holds logical gmem
// float4 group QPERM(i); window LDS.128s become lane-contiguous.
#define QPERM(i) (((i) < 16) ? (2 * (i) + 1) : (2 * ((i) - 16)))

__device__ float g_partials[GRIDB];
__device__ int g_ctr = 0;

// Full 16-half2 window (physical chunks tx, 17+tx, tx+1, 18+tx).
#define LOADROW(wdst, srow, txv)                                                   \
    do {                                                                           \
        const float4* rowp = reinterpret_cast<const float4*>(&(srow)[0]);          \
        float4 v0 = rowp[(txv)];                                                   \
        float4 v1 = rowp[17 + (txv)];                                              \
        float4 v2 = rowp[(txv) + 1];                                               \
        float4 v3 = rowp[18 + (txv)];                                              \
        (wdst)[0] = *(__half2*)&v0.x;  (wdst)[1] = *(__half2*)&v0.y;               \
        (wdst)[2] = *(__half2*)&v0.z;  (wdst)[3] = *(__half2*)&v0.w;               \
        (wdst)[4] = *(__half2*)&v1.x;  (wdst)[5] = *(__half2*)&v1.y;               \
        (wdst)[6] = *(__half2*)&v1.z;  (wdst)[7] = *(__half2*)&v1.w;               \
        (wdst)[8] = *(__half2*)&v2.x;  (wdst)[9] = *(__half2*)&v2.y;               \
        (wdst)[10] = *(__half2*)&v2.z; (wdst)[11] = *(__half2*)&v2.w;              \
        (wdst)[12] = *(__half2*)&v3.x; (wdst)[13] = *(__half2*)&v3.y;              \
        (wdst)[14] = *(__half2*)&v3.z; (wdst)[15] = *(__half2*)&v3.w;              \
    } while (0)

// k=0 needs only w[4..15] (dl >= 0): 3 LDS.128.
#define LOADROW_K0(wdst, srow, txv)                                                \
    do {                                                                           \
        const float4* rowp = reinterpret_cast<const float4*>(&(srow)[0]);          \
        float4 v1 = rowp[17 + (txv)];                                              \
        float4 v2 = rowp[(txv) + 1];                                               \
        float4 v3 = rowp[18 + (txv)];                                              \
        (wdst)[4] = *(__half2*)&v1.x;  (wdst)[5] = *(__half2*)&v1.y;               \
        (wdst)[6] = *(__half2*)&v1.z;  (wdst)[7] = *(__half2*)&v1.w;               \
        (wdst)[8] = *(__half2*)&v2.x;  (wdst)[9] = *(__half2*)&v2.y;               \
        (wdst)[10] = *(__half2*)&v2.z; (wdst)[11] = *(__half2*)&v2.w;              \
        (wdst)[12] = *(__half2*)&v3.x; (wdst)[13] = *(__half2*)&v3.y;              \
        (wdst)[14] = *(__half2*)&v3.z; (wdst)[15] = *(__half2*)&v3.w;              \
    } while (0)

#define ACCUM(ac, cc, wv, DL0)                                                     \
    do {                                                                           \
        _Pragma("unroll")                                                          \
        for (int dl = (DL0); dl <= 3; dl++) {                                      \
            _Pragma("unroll")                                                      \
            for (int e = 0; e < RE; e++) {                                         \
                __half2 d = __habs2(__hsub2((cc)[e], (wv)[4 + e + dl]));           \
                (ac)[e] = __hadd2((ac)[e], d);                                     \
            }                                                                      \
        }                                                                          \
    } while (0)

__global__ __launch_bounds__(THREADS, 3) void btv_kernel(const float* __restrict__ x,
                                                         float* __restrict__ out) {
    __shared__ __align__(16) __half2 s[2][PROWS][SCOLS];
    __shared__ float warp_sums[THREADS / 32];
    __shared__ int s_last;

    const int tid = threadIdx.x;
    const int tx = tid & 15;
    const int ty = (tid >> 4) & 15;    // valid for compute threads (tid < 256)
    const int ptid = tid - NCOMP;      // producer index 0..63 (tid >= 256)

    float accf = 0.0f;

    // ---- Producer: load tile tt into buffer buf ----
    auto produce = [&](int tt, int buf) {
        int px_ = tt & (NBX - 1), py_ = (tt >> 3) & (NBY - 1), pz_ = tt >> 8;
        int txx = px_ * TW, tyy = py_ * THRAW;
        const float* pl = x + (size_t)pz_ * (H * W);
        const float4* pp = reinterpret_cast<const float4*>(pl);
#pragma unroll 1
        for (int g = ptid; g < NGRP; g += NPROD) {
            int r = g >> 5, i = g & 31;
            int q = QPERM(i);
            float4 a = pp[(((tyy + r) & (H - 1)) * (W / 4)) + (txx >> 2) + q];
            float4 b = pp[(((tyy + r + PACK) & (H - 1)) * (W / 4)) + (txx >> 2) + q];
            __half2 h0 = __floats2half2_rn(a.x, b.x);
            __half2 h1 = __floats2half2_rn(a.y, b.y);
            __half2 h2 = __floats2half2_rn(a.z, b.z);
            __half2 h3 = __floats2half2_rn(a.w, b.w);
            float4 st;
            st.x = *(float*)&h0; st.y = *(float*)&h1;
            st.z = *(float*)&h2; st.w = *(float*)&h3;
            *reinterpret_cast<float4*>(&s[buf][r][4 + 4 * i]) = st;
        }
#pragma unroll 1
        for (int h = ptid; h < NHALO; h += NPROD) {
            int r = h >> 3, hcp = h & 7;
            int c = (hcp < 4) ? hcp : (128 + hcp);
            int gc = (txx + c - 4) & (W - 1);
            float va = pl[(((tyy + r) & (H - 1)) * W) + gc];
            float vb = pl[(((tyy + r + PACK) & (H - 1)) * W) + gc];
            s[buf][r][c] = __floats2half2_rn(va, vb);
        }
    };

    int t = blockIdx.x;

    // Prologue: producers fill buffer 0 with tile t.
    if (tid >= NCOMP) produce(t, 0);
    __syncthreads();

    int cb = 0;
#pragma unroll 1
    for (; t < NT; t += GRIDB) {
        const int tn = t + GRIDB;

        if (tid < NCOMP) {
            // ---- Consumer: pure compute from s[cb] ----
            __half2 c2[RE];
            __half2 acc[RE];
#pragma unroll
            for (int e = 0; e < RE; e++) acc[e] = __floats2half2_rn(0.0f, 0.0f);

            __half2 win[16];

            // k = 0: centers + dl = 1..3 (symmetry covers negatives)
            LOADROW_K0(win, s[cb][ty], tx);
#pragma unroll
            for (int e = 0; e < RE; e++) c2[e] = win[4 + e];
            ACCUM(acc, c2, win, 1);

            LOADROW(win, s[cb][ty + 1], tx);
            ACCUM(acc, c2, win, -3);

            LOADROW(win, s[cb][ty + 2], tx);
            ACCUM(acc, c2, win, -3);

            LOADROW(win, s[cb][ty + 3], tx);
            ACCUM(acc, c2, win, -3);

            // Drain fp16 accumulators to fp32 per tile.
#pragma unroll
            for (int e = 0; e < RE; e++) {
                float2 f = __half22float2(acc[e]);
                accf += f.x + f.y;
            }
        } else {
            // ---- Producer: fill the other buffer with the next tile ----
            if (tn < NT) produce(tn, cb ^ 1);
        }

        __syncthreads();
        cb ^= 1;
    }

    // ---- Block reduction (producers contribute 0) ----
#pragma unroll
    for (int o = 16; o > 0; o >>= 1) accf += __shfl_down_sync(0xFFFFFFFFu, accf, o);

    const int lane = tid & 31;
    const int wid = tid >> 5;
    if (lane == 0) warp_sums[wid] = accf;
    __syncthreads();

    if (tid == 0) {
        float bsum = 0.0f;
#pragma unroll
        for (int i = 0; i < THREADS / 32; i++) bsum += warp_sums[i];
        g_partials[blockIdx.x] = bsum;
        __threadfence();
        int done = atomicAdd(&g_ctr, 1);
        s_last = (done == GRIDB - 1) ? 1 : 0;
    }
    __syncthreads();

    // Last block reduces all partials (fixed order -> deterministic)
    if (s_last) {
        double td = 0.0;
        for (int i = tid; i < GRIDB; i += THREADS) td += (double)g_partials[i];
#pragma unroll
        for (int o = 16; o > 0; o >>= 1) td += __shfl_down_sync(0xFFFFFFFFu, td, o);
        __shared__ double sm[THREADS / 32];
        if (lane == 0) sm[wid] = td;
        __syncthreads();
        if (tid == 0) {
            double r = 0.0;
#pragma unroll
            for (int i = 0; i < THREADS / 32; i++) r += sm[i];
            // symmetry factor 2; WEIGHT=0.1; N = 24*1024*1024
            out[0] = (float)(r * (0.2 / 25165824.0));
            atomicExch(&g_ctr, 0);  // reset for next graph replay
        }
    }
}

extern "C" void kernel_launch(void* const* d_in, const int* in_sizes, int n_in,
                              void* d_out, int out_size) {
    (void)in_sizes; (void)n_in; (void)out_size;
    const float* x = (const float*)d_in[0];
    float* out = (float*)d_out;

    btv_kernel<<<GRIDB, THREADS>>>(x, out);
}

// round 16
// speedup vs baseline: 1.9805x; 1.9805x over previous
#include <cuda_runtime.h>
#include <cuda_fp16.h>

#define H 1024
#define W 1024
#define PLANES 24              // 8 * 3
#define THRAW 32               // raw output rows per tile
#define PACK 16                // row-pack stride (.x = r, .y = r+16)
#define TW 128                 // tile cols
#define RE 8                   // cols per thread
#define BX 16
#define BY 16                  // packed rows per tile (compute threads = 256)
#define NCOMP 256
#define NPROD 128              // 4 producer warps
#define THREADS (NCOMP + NPROD)  // 384
#define PROWS (BY + 3)         // 19
#define SCOLS (TW + 8)         // 136 half2 = 34 16B-chunks per row
#define NBX (W / TW)           // 8
#define NBY (H / THRAW)        // 32
#define NT (NBX * NBY * PLANES)       // 6144 tiles
#define GRIDB 444              // 148 SMs x 3 resident blocks
#define NGRP (PROWS * (TW / 4))       // 608 interior float4-groups
#define NHALO (PROWS * 8)             // 152 halo half2 entries

// Even/odd chunk de-interleave: physical slot i (0..31) holds logical gmem
// float4 group QPERM(i); window LDS.128s become lane-contiguous.
#define QPERM(i) (((i) < 16) ? (2 * (i) + 1) : (2 * ((i) - 16)))

__device__ float g_partials[GRIDB];
__device__ int g_ctr = 0;

// Full 16-half2 window (physical chunks tx, 17+tx, tx+1, 18+tx).
#define LOADROW(wdst, srow, txv)                                                   \
    do {                                                                           \
        const float4* rowp = reinterpret_cast<const float4*>(&(srow)[0]);          \
        float4 v0 = rowp[(txv)];                                                   \
        float4 v1 = rowp[17 + (txv)];                                              \
        float4 v2 = rowp[(txv) + 1];                                               \
        float4 v3 = rowp[18 + (txv)];                                              \
        (wdst)[0] = *(__half2*)&v0.x;  (wdst)[1] = *(__half2*)&v0.y;               \
        (wdst)[2] = *(__half2*)&v0.z;  (wdst)[3] = *(__half2*)&v0.w;               \
        (wdst)[4] = *(__half2*)&v1.x;  (wdst)[5] = *(__half2*)&v1.y;               \
        (wdst)[6] = *(__half2*)&v1.z;  (wdst)[7] = *(__half2*)&v1.w;               \
        (wdst)[8] = *(__half2*)&v2.x;  (wdst)[9] = *(__half2*)&v2.y;               \
        (wdst)[10] = *(__half2*)&v2.z; (wdst)[11] = *(__half2*)&v2.w;              \
        (wdst)[12] = *(__half2*)&v3.x; (wdst)[13] = *(__half2*)&v3.y;              \
        (wdst)[14] = *(__half2*)&v3.z; (wdst)[15] = *(__half2*)&v3.w;              \
    } while (0)

// k=0 needs only w[4..15] (dl >= 0): 3 LDS.128.
#define LOADROW_K0(wdst, srow, txv)                                                \
    do {                                                                           \
        const float4* rowp = reinterpret_cast<const float4*>(&(srow)[0]);          \
        float4 v1 = rowp[17 + (txv)];                                              \
        float4 v2 = rowp[(txv) + 1];                                               \
        float4 v3 = rowp[18 + (txv)];                                              \
        (wdst)[4] = *(__half2*)&v1.x;  (wdst)[5] = *(__half2*)&v1.y;               \
        (wdst)[6] = *(__half2*)&v1.z;  (wdst)[7] = *(__half2*)&v1.w;               \
        (wdst)[8] = *(__half2*)&v2.x;  (wdst)[9] = *(__half2*)&v2.y;               \
        (wdst)[10] = *(__half2*)&v2.z; (wdst)[11] = *(__half2*)&v2.w;              \
        (wdst)[12] = *(__half2*)&v3.x; (wdst)[13] = *(__half2*)&v3.y;              \
        (wdst)[14] = *(__half2*)&v3.z; (wdst)[15] = *(__half2*)&v3.w;              \
    } while (0)

#define ACCUM(ac, cc, wv, DL0)                                                     \
    do {                                                                           \
        _Pragma("unroll")                                                          \
        for (int dl = (DL0); dl <= 3; dl++) {                                      \
            _Pragma("unroll")                                                      \
            for (int e = 0; e < RE; e++) {                                         \
                __half2 d = __habs2(__hsub2((cc)[e], (wv)[4 + e + dl]));           \
                (ac)[e] = __hadd2((ac)[e], d);                                     \
            }                                                                      \
        }                                                                          \
    } while (0)

__global__ __launch_bounds__(THREADS, 3) void btv_kernel(const float* __restrict__ x,
                                                         float* __restrict__ out) {
    __shared__ __align__(16) __half2 s[2][PROWS][SCOLS];
    __shared__ float warp_sums[THREADS / 32];
    __shared__ int s_last;

    const int tid = threadIdx.x;
    const int tx = tid & 15;
    const int ty = (tid >> 4) & 15;    // valid for compute threads (tid < 256)
    const int ptid = tid - NCOMP;      // producer index 0..127 (tid >= 256)

    float accf = 0.0f;

    // ---- Producer: load tile tt into buffer buf. All LDGs batched first
    //      (registers), then converted + stored: MLP ~12 per thread. ----
    auto produce = [&](int tt, int buf) {
        int px_ = tt & (NBX - 1), py_ = (tt >> 3) & (NBY - 1), pz_ = tt >> 8;
        int txx = px_ * TW, tyy = py_ * THRAW;
        const float* pl = x + (size_t)pz_ * (H * W);
        const float4* pp = reinterpret_cast<const float4*>(pl);

        float4 a[5], b[5];
        float ha0, hb0, ha1 = 0.0f, hb1 = 0.0f;
        const bool g5 = (ptid < NGRP - 512);     // 96 tail groups
        const bool h1v = (ptid < NHALO - 128);   // 24 tail halo entries

        // --- batch all loads ---
#pragma unroll
        for (int j = 0; j < 4; j++) {
            int g = ptid + 128 * j;
            int r = g >> 5, i = g & 31;
            int q = QPERM(i);
            a[j] = pp[(((tyy + r) & (H - 1)) * (W / 4)) + (txx >> 2) + q];
            b[j] = pp[(((tyy + r + PACK) & (H - 1)) * (W / 4)) + (txx >> 2) + q];
        }
        if (g5) {
            int g = ptid + 512;
            int r = g >> 5, i = g & 31;
            int q = QPERM(i);
            a[4] = pp[(((tyy + r) & (H - 1)) * (W / 4)) + (txx >> 2) + q];
            b[4] = pp[(((tyy + r + PACK) & (H - 1)) * (W / 4)) + (txx >> 2) + q];
        }
        {
            int r = ptid >> 3, hcp = ptid & 7;
            int c = (hcp < 4) ? hcp : (128 + hcp);
            int gc = (txx + c - 4) & (W - 1);
            ha0 = pl[(((tyy + r) & (H - 1)) * W) + gc];
            hb0 = pl[(((tyy + r + PACK) & (H - 1)) * W) + gc];
        }
        if (h1v) {
            int h = ptid + 128;
            int r = h >> 3, hcp = h & 7;
            int c = (hcp < 4) ? hcp : (128 + hcp);
            int gc = (txx + c - 4) & (W - 1);
            ha1 = pl[(((tyy + r) & (H - 1)) * W) + gc];
            hb1 = pl[(((tyy + r + PACK) & (H - 1)) * W) + gc];
        }

        // --- convert + store ---
#pragma unroll
        for (int j = 0; j < 4; j++) {
            int g = ptid + 128 * j;
            int r = g >> 5, i = g & 31;
            __half2 h0 = __floats2half2_rn(a[j].x, b[j].x);
            __half2 h1 = __floats2half2_rn(a[j].y, b[j].y);
            __half2 h2 = __floats2half2_rn(a[j].z, b[j].z);
            __half2 h3 = __floats2half2_rn(a[j].w, b[j].w);
            float4 st;
            st.x = *(float*)&h0; st.y = *(float*)&h1;
            st.z = *(float*)&h2; st.w = *(float*)&h3;
            *reinterpret_cast<float4*>(&s[buf][r][4 + 4 * i]) = st;
        }
        if (g5) {
            int g = ptid + 512;
            int r = g >> 5, i = g & 31;
            __half2 h0 = __floats2half2_rn(a[4].x, b[4].x);
            __half2 h1 = __floats2half2_rn(a[4].y, b[4].y);
            __half2 h2 = __floats2half2_rn(a[4].z, b[4].z);
            __half2 h3 = __floats2half2_rn(a[4].w, b[4].w);
            float4 st;
            st.x = *(float*)&h0; st.y = *(float*)&h1;
            st.z = *(float*)&h2; st.w = *(float*)&h3;
            *reinterpret_cast<float4*>(&s[buf][r][4 + 4 * i]) = st;
        }
        {
            int r = ptid >> 3, hcp = ptid & 7;
            int c = (hcp < 4) ? hcp : (128 + hcp);
            s[buf][r][c] = __floats2half2_rn(ha0, hb0);
        }
        if (h1v) {
            int h = ptid + 128;
            int r = h >> 3, hcp = h & 7;
            int c = (hcp < 4) ? hcp : (128 + hcp);
            s[buf][r][c] = __floats2half2_rn(ha1, hb1);
        }
    };

    int t = blockIdx.x;

    // Prologue: producers fill buffer 0 with tile t.
    if (tid >= NCOMP) produce(t, 0);
    __syncthreads();

    int cb = 0;
#pragma unroll 1
    for (; t < NT; t += GRIDB) {
        const int tn = t + GRIDB;

        if (tid < NCOMP) {
            // ---- Consumer: pure LDS + fma from s[cb] ----
            __half2 c2[RE];
            __half2 acc[RE];
#pragma unroll
            for (int e = 0; e < RE; e++) acc[e] = __floats2half2_rn(0.0f, 0.0f);

            __half2 win[16];

            // k = 0: centers + dl = 1..3 (symmetry covers negatives)
            LOADROW_K0(win, s[cb][ty], tx);
#pragma unroll
            for (int e = 0; e < RE; e++) c2[e] = win[4 + e];
            ACCUM(acc, c2, win, 1);

            LOADROW(win, s[cb][ty + 1], tx);
            ACCUM(acc, c2, win, -3);

            LOADROW(win, s[cb][ty + 2], tx);
            ACCUM(acc, c2, win, -3);

            LOADROW(win, s[cb][ty + 3], tx);
            ACCUM(acc, c2, win, -3);

            // Drain fp16 accumulators to fp32 per tile.
#pragma unroll
            for (int e = 0; e < RE; e++) {
                float2 f = __half22float2(acc[e]);
                accf += f.x + f.y;
            }
        } else {
            // ---- Producer: fill the other buffer with the next tile ----
            if (tn < NT) produce(tn, cb ^ 1);
        }

        __syncthreads();
        cb ^= 1;
    }

    // ---- Block reduction (producers contribute 0) ----
#pragma unroll
    for (int o = 16; o > 0; o >>= 1) accf += __shfl_down_sync(0xFFFFFFFFu, accf, o);

    const int lane = tid & 31;
    const int wid = tid >> 5;
    if (lane == 0) warp_sums[wid] = accf;
    __syncthreads();

    if (tid == 0) {
        float bsum = 0.0f;
#pragma unroll
        for (int i = 0; i < THREADS / 32; i++) bsum += warp_sums[i];
        g_partials[blockIdx.x] = bsum;
        __threadfence();
        int done = atomicAdd(&g_ctr, 1);
        s_last = (done == GRIDB - 1) ? 1 : 0;
    }
    __syncthreads();

    // Last block reduces all partials (fixed order -> deterministic)
    if (s_last) {
        double td = 0.0;
        for (int i = tid; i < GRIDB; i += THREADS) td += (double)g_partials[i];
#pragma unroll
        for (int o = 16; o > 0; o >>= 1) td += __shfl_down_sync(0xFFFFFFFFu, td, o);
        __shared__ double sm[THREADS / 32];
        if (lane == 0) sm[wid] = td;
        __syncthreads();
        if (tid == 0) {
            double r = 0.0;
#pragma unroll
            for (int i = 0; i < THREADS / 32; i++) r += sm[i];
            // symmetry factor 2; WEIGHT=0.1; N = 24*1024*1024
            out[0] = (float)(r * (0.2 / 25165824.0));
            atomicExch(&g_ctr, 0);  // reset for next graph replay
        }
    }
}

extern "C" void kernel_launch(void* const* d_in, const int* in_sizes, int n_in,
                              void* d_out, int out_size) {
    (void)in_sizes; (void)n_in; (void)out_size;
    const float* x = (const float*)d_in[0];
    float* out = (float*)d_out;

    btv_kernel<<<GRIDB, THREADS>>>(x, out);
}